// round 6
// baseline (speedup 1.0000x reference)
#include <cuda_runtime.h>
#include <cuda_bf16.h>
#include <cstdint>

// Problem constants
#define BB 32
#define SS 1024
#define HH 1024
#define EE 512
#define VV 32000
// Output layout (float32): prediction (B,1,V) | h_new (1,B,H) | c_new (1,B,H) | weights (B,S)
#define OFF_PRED 0
#define OFF_H    1024000
#define OFF_C    1056768
#define OFF_W    1089536

// ---------------- scratch (__device__ globals; no allocation allowed) ----------------
__device__ float g_u[BB * HH];          // W1 @ h + attn_b, per (b,h)
__device__ float g_scores[BB * SS];     // pre-softmax attention scores
__device__ float g_ziT[3584 * BB];      // [k][b] transposed LSTM input: emb(512)|context(2048)|hidden(1024)
__device__ float g_gates[BB * 4096];    // LSTM gates
__device__ float g_hnT[HH * BB];        // [h][b] transposed h_new for fc GEMM

// ---------------- helpers ----------------
__device__ __forceinline__ float sigf(float x) { return 1.0f / (1.0f + __expf(-x)); }

__device__ __forceinline__ unsigned long long pk2(float lo, float hi) {
    unsigned long long r; asm("mov.b64 %0, {%1, %2};" : "=l"(r) : "f"(lo), "f"(hi)); return r;
}
__device__ __forceinline__ void fma2(unsigned long long& c, unsigned long long a, unsigned long long b) {
    asm("fma.rn.f32x2 %0, %1, %2, %0;" : "+l"(c) : "l"(a), "l"(b));
}
__device__ __forceinline__ float2 upk2(unsigned long long v) {
    float lo, hi; asm("mov.b64 {%0, %1}, %2;" : "=f"(lo), "=f"(hi) : "l"(v));
    return make_float2(lo, hi);
}

// ---------------- kernel A: u[b,h] = attn_b[h] + sum_k hidden[b,k] * attn_W[h,k] ----------------
// grid 128, block 256 (8 warps). Warp w handles h = blk*8 + w for ALL 32 b (lanes stride k).
__global__ void u_kernel(const float* __restrict__ hidden, const float* __restrict__ attn_W,
                         const float* __restrict__ attn_b) {
    int w = threadIdx.x >> 5, lane = threadIdx.x & 31;
    int h = blockIdx.x * 8 + w;
    const float* Wr = attn_W + (size_t)h * 3072;  // first HH columns = W1
    float acc[32];
#pragma unroll
    for (int b = 0; b < 32; b++) acc[b] = 0.f;
    for (int kc = 0; kc < HH; kc += 32) {
        float wv = Wr[kc + lane];
#pragma unroll
        for (int b = 0; b < 32; b++) acc[b] += wv * __ldg(&hidden[b * HH + kc + lane]);
    }
    float bias = attn_b[h];
#pragma unroll
    for (int b = 0; b < 32; b++) {
        float s = acc[b];
#pragma unroll
        for (int o = 16; o; o >>= 1) s += __shfl_xor_sync(0xffffffffu, s, o);
        if (lane == b) g_u[b * HH + h] = s + bias;
    }
}

// ---------------- kernel: embed gather + hidden copy into transposed ziT ----------------
// grid 32 (b), block 512
__global__ void embed_kernel(const int* __restrict__ x, const float* __restrict__ emb,
                             const float* __restrict__ hidden) {
    int b = blockIdx.x, t = threadIdx.x;
    int row = x[b];
    g_ziT[t * BB + b] = emb[(size_t)row * EE + t];                 // t in [0,512)
    for (int k = t; k < HH; k += 512)
        g_ziT[(2560 + k) * BB + b] = hidden[b * HH + k];
}

// ---------------- kernel B: fused  scores[b,s] = sum_h v[h]*tanh(u[b,h] + enc[b,s,:] @ W2[h,:]) ----
// grid (32 b, 8 s-tiles), block 256. Tile: 128 s-rows x 128 h-cols per iteration, K=2048, 8 h-tiles.
// fp32 via packed f32x2 FFMA. Deterministic (register accumulation + fixed shfl reduce).
__global__ void __launch_bounds__(256, 2)
score_kernel(const float* __restrict__ enc, const float* __restrict__ attn_W,
             const float* __restrict__ v_W) {
    int b = blockIdx.x;
    int st = blockIdx.y;
    const float* A = enc + ((size_t)b * SS + st * 128) * 2048;

    __shared__ __align__(16) float As[32][128];
    __shared__ __align__(16) float Bs[32][128];
    __shared__ float vs[128], us[128];

    int tid = threadIdx.x;
    int tx = tid & 15, ty = tid >> 4;

    float sc[8];
#pragma unroll
    for (int i = 0; i < 8; i++) sc[i] = 0.f;

    for (int ht = 0; ht < 8; ht++) {
        int h0 = ht * 128;
        if (tid < 128) {
            vs[tid] = v_W[h0 + tid];
            us[tid] = g_u[b * HH + h0 + tid];
        }
        unsigned long long acc[8][4];
#pragma unroll
        for (int i = 0; i < 8; i++)
#pragma unroll
            for (int j = 0; j < 4; j++) acc[i][j] = 0ull;

        for (int kc = 0; kc < 2048; kc += 32) {
            __syncthreads();
#pragma unroll
            for (int l = 0; l < 16; l++) {
                int e = l * 256 + tid;
                int r = e >> 5, k = e & 31;
                As[k][r] = A[(size_t)r * 2048 + kc + k];
                Bs[k][r] = attn_W[(size_t)(h0 + r) * 3072 + 1024 + kc + k];
            }
            __syncthreads();
#pragma unroll
            for (int k = 0; k < 32; k++) {
                float4 a0 = *(const float4*)&As[k][ty * 8];
                float4 a1 = *(const float4*)&As[k][ty * 8 + 4];
                float4 b0 = *(const float4*)&Bs[k][tx * 8];
                float4 b1 = *(const float4*)&Bs[k][tx * 8 + 4];
                unsigned long long bp[4] = {pk2(b0.x, b0.y), pk2(b0.z, b0.w),
                                            pk2(b1.x, b1.y), pk2(b1.z, b1.w)};
                float av[8] = {a0.x, a0.y, a0.z, a0.w, a1.x, a1.y, a1.z, a1.w};
#pragma unroll
                for (int i = 0; i < 8; i++) {
                    unsigned long long ap = pk2(av[i], av[i]);
#pragma unroll
                    for (int j = 0; j < 4; j++) fma2(acc[i][j], ap, bp[j]);
                }
            }
        }
        // epilogue: accurate tanh + weighted reduce into per-row partial (register-resident)
#pragma unroll
        for (int i = 0; i < 8; i++) {
            float local = 0.f;
#pragma unroll
            for (int j = 0; j < 4; j++) {
                float2 e = upk2(acc[i][j]);
                int c0 = tx * 8 + 2 * j;
                local += vs[c0] * tanhf(us[c0] + e.x);
                local += vs[c0 + 1] * tanhf(us[c0 + 1] + e.y);
            }
            sc[i] += local;
        }
        __syncthreads();
    }
    // reduce across tx (16 lanes, two independent halves per warp)
#pragma unroll
    for (int i = 0; i < 8; i++) {
        float v = sc[i];
#pragma unroll
        for (int o = 8; o; o >>= 1) v += __shfl_down_sync(0xffffffffu, v, o, 16);
        if (tx == 0) g_scores[b * SS + st * 128 + ty * 8 + i] = v;
    }
}

// ---------------- kernel C: softmax over S per batch; writes weights into d_out ----------------
// grid 32, block 1024
__global__ void softmax_kernel(float* __restrict__ d_out) {
    int b = blockIdx.x, t = threadIdx.x;
    int lane = t & 31, wp = t >> 5;
    __shared__ float red[32];
    __shared__ float bc;
    float x = g_scores[b * SS + t];

    float m = x;
#pragma unroll
    for (int o = 16; o; o >>= 1) m = fmaxf(m, __shfl_xor_sync(0xffffffffu, m, o));
    if (!lane) red[wp] = m;
    __syncthreads();
    if (t < 32) {
        float mm = red[t];
#pragma unroll
        for (int o = 16; o; o >>= 1) mm = fmaxf(mm, __shfl_xor_sync(0xffffffffu, mm, o));
        if (!t) bc = mm;
    }
    __syncthreads();
    float M = bc;
    float e = __expf(x - M);
    __syncthreads();
    float s = e;
#pragma unroll
    for (int o = 16; o; o >>= 1) s += __shfl_xor_sync(0xffffffffu, s, o);
    if (!lane) red[wp] = s;
    __syncthreads();
    if (t < 32) {
        float ss = red[t];
#pragma unroll
        for (int o = 16; o; o >>= 1) ss += __shfl_xor_sync(0xffffffffu, ss, o);
        if (!t) bc = ss;
    }
    __syncthreads();
    d_out[OFF_W + b * SS + t] = e / bc;
}

// ---------------- kernel D: context[b,d] = sum_s w[b,s]*enc[b,s,d]; writes into ziT ----------------
// grid (8 d-chunks, 32 b), block 256
__global__ void context_kernel(const float* __restrict__ enc, const float* __restrict__ d_out) {
    int b = blockIdx.y;
    int d = blockIdx.x * 256 + threadIdx.x;
    const float* E = enc + (size_t)b * SS * 2048 + d;
    const float* W = d_out + OFF_W + b * SS;
    float acc = 0.f;
    for (int s = 0; s < SS; s += 8) {
#pragma unroll
        for (int u = 0; u < 8; u++) acc += W[s + u] * E[(size_t)(s + u) * 2048];
    }
    g_ziT[(512 + d) * BB + b] = acc;
}

// ---------------- kernel E: gates GEMM: (4096 rows) x (32 b), K = 3584 = 2560(W_ih)|1024(W_hh) ----
// grid 128 (32 rows each), block 256: micro 2 rows x 2 b
__global__ void gates_kernel(const float* __restrict__ W_ih, const float* __restrict__ W_hh,
                             const float* __restrict__ b_ih, const float* __restrict__ b_hh) {
    __shared__ float Ws[32][32];
    __shared__ float Zs[32][32];
    int tid = threadIdx.x;
    int tx = tid & 15, ty = tid >> 4;
    int g0 = blockIdx.x * 32;
    float acc[2][2] = {{0.f, 0.f}, {0.f, 0.f}};

    for (int kc = 0; kc < 3584; kc += 32) {
        __syncthreads();
#pragma unroll
        for (int l = 0; l < 4; l++) {
            int e = l * 256 + tid;
            int r = e >> 5, k = e & 31;
            int kg = kc + k;
            Ws[k][r] = (kc < 2560) ? W_ih[(size_t)(g0 + r) * 2560 + kg]
                                   : W_hh[(size_t)(g0 + r) * 1024 + kg - 2560];
            // g_ziT is [K][b] linear (K*32+b): element e of this tile is
            // K = kc + (e>>5), b = e&31  ->  store as Zs[K_local][b].
            Zs[e >> 5][e & 31] = g_ziT[(size_t)kc * 32 + e];
        }
        __syncthreads();
#pragma unroll
        for (int k = 0; k < 32; k++) {
            float a0 = Ws[k][ty * 2], a1 = Ws[k][ty * 2 + 1];
            float z0 = Zs[k][tx * 2], z1 = Zs[k][tx * 2 + 1];
            acc[0][0] += a0 * z0; acc[0][1] += a0 * z1;
            acc[1][0] += a1 * z0; acc[1][1] += a1 * z1;
        }
    }
#pragma unroll
    for (int i = 0; i < 2; i++) {
        int g = g0 + ty * 2 + i;
        float bias = b_ih[g] + b_hh[g];
#pragma unroll
        for (int j = 0; j < 2; j++) {
            int bcol = tx * 2 + j;
            g_gates[bcol * 4096 + g] = acc[i][j] + bias;
        }
    }
}

// ---------------- kernel: LSTM elementwise ----------------
// grid 128, block 256
__global__ void lstm_elt_kernel(const float* __restrict__ cell, float* __restrict__ d_out) {
    int idx = blockIdx.x * 256 + threadIdx.x;  // 32768
    int b = idx >> 10, h = idx & 1023;
    const float* g = g_gates + b * 4096;
    float gi = g[h], gf = g[1024 + h], gg = g[2048 + h], go = g[3072 + h];
    float c = cell[idx];
    float cn = sigf(gf) * c + sigf(gi) * tanhf(gg);
    float hn = sigf(go) * tanhf(cn);
    d_out[OFF_H + idx] = hn;
    d_out[OFF_C + idx] = cn;
    g_hnT[h * BB + b] = hn;
}

// ---------------- kernel F: fc GEMM: (32000 rows) x (32 b), K = 1024 ----------------
// grid 500 (64 rows each), block 256: micro 2 rows x 4 b
__global__ void fc_kernel(const float* __restrict__ fc_W, const float* __restrict__ fc_b,
                          float* __restrict__ d_out) {
    __shared__ __align__(16) float Ws[32][64];
    __shared__ __align__(16) float Zs[32][32];
    int tid = threadIdx.x;
    int tx = tid & 7, ty = tid >> 3;  // tx: b quad, ty: row pair (0..31)
    int v0 = blockIdx.x * 64;
    float acc[2][4];
#pragma unroll
    for (int i = 0; i < 2; i++)
#pragma unroll
        for (int j = 0; j < 4; j++) acc[i][j] = 0.f;

    for (int kc = 0; kc < 1024; kc += 32) {
        __syncthreads();
#pragma unroll
        for (int l = 0; l < 8; l++) {
            int e = l * 256 + tid;
            int r = e >> 5, k = e & 31;
            Ws[k][r] = fc_W[(size_t)(v0 + r) * 1024 + kc + k];
        }
#pragma unroll
        for (int l = 0; l < 4; l++) {
            int e = l * 256 + tid;
            Zs[e >> 5][e & 31] = g_hnT[(size_t)kc * 32 + e];
        }
        __syncthreads();
#pragma unroll
        for (int k = 0; k < 32; k++) {
            float a0 = Ws[k][ty * 2], a1 = Ws[k][ty * 2 + 1];
            float4 z = *(const float4*)&Zs[k][tx * 4];
            acc[0][0] += a0 * z.x; acc[0][1] += a0 * z.y; acc[0][2] += a0 * z.z; acc[0][3] += a0 * z.w;
            acc[1][0] += a1 * z.x; acc[1][1] += a1 * z.y; acc[1][2] += a1 * z.z; acc[1][3] += a1 * z.w;
        }
    }
#pragma unroll
    for (int i = 0; i < 2; i++) {
        int v = v0 + ty * 2 + i;
        float bias = fc_b[v];
#pragma unroll
        for (int j = 0; j < 4; j++) {
            int bcol = tx * 4 + j;
            d_out[OFF_PRED + (size_t)bcol * VV + v] = acc[i][j] + bias;
        }
    }
}

// ---------------- launcher ----------------
extern "C" void kernel_launch(void* const* d_in, const int* in_sizes, int n_in,
                              void* d_out_v, int out_size) {
    const int*   x      = (const int*)d_in[0];
    const float* hidden = (const float*)d_in[1];
    const float* cell   = (const float*)d_in[2];
    const float* enc    = (const float*)d_in[3];
    const float* emb    = (const float*)d_in[4];
    const float* attn_W = (const float*)d_in[5];
    const float* attn_b = (const float*)d_in[6];
    const float* v_W    = (const float*)d_in[7];
    const float* W_ih   = (const float*)d_in[8];
    const float* W_hh   = (const float*)d_in[9];
    const float* b_ih   = (const float*)d_in[10];
    const float* b_hh   = (const float*)d_in[11];
    const float* fc_W   = (const float*)d_in[12];
    const float* fc_b   = (const float*)d_in[13];
    float* d_out = (float*)d_out_v;

    u_kernel<<<128, 256>>>(hidden, attn_W, attn_b);
    embed_kernel<<<32, 512>>>(x, emb, hidden);
    score_kernel<<<dim3(32, 8), 256>>>(enc, attn_W, v_W);
    softmax_kernel<<<32, 1024>>>(d_out);
    context_kernel<<<dim3(8, 32), 256>>>(enc, d_out);
    gates_kernel<<<128, 256>>>(W_ih, W_hh, b_ih, b_hh);
    lstm_elt_kernel<<<128, 256>>>(cell, d_out);
    fc_kernel<<<500, 256>>>(fc_W, fc_b, d_out);
}

// round 8
// speedup vs baseline: 3.8620x; 3.8620x over previous
#include <cuda_runtime.h>
#include <cuda_bf16.h>
#include <cstdint>

// Problem constants
#define BB 32
#define SS 1024
#define HH 1024
#define EE 512
#define VV 32000
// Output layout (float32): prediction (B,1,V) | h_new (1,B,H) | c_new (1,B,H) | weights (B,S)
#define OFF_PRED 0
#define OFF_H    1024000
#define OFF_C    1056768
#define OFF_W    1089536

// ---------------- scratch (__device__ globals; no allocation allowed) ----------------
__device__ float g_u[BB * HH];          // W1 @ h + attn_b, per (b,h)
__device__ float g_scores[BB * SS];     // pre-softmax attention scores
__device__ float g_ziT[3584 * BB];      // [k][b] transposed LSTM input: emb(512)|context(2048)|hidden(1024)
__device__ float g_gates[BB * 4096];    // LSTM gates
__device__ float g_hnT[HH * BB];        // [h][b] transposed h_new for fc GEMM
__device__ __nv_bfloat16 g_W2hi[1024 * 2048];  // bf16 split of attn_W[:,1024:3072]
__device__ __nv_bfloat16 g_W2lo[1024 * 2048];

// ---------------- helpers ----------------
__device__ __forceinline__ float sigf(float x) { return 1.0f / (1.0f + __expf(-x)); }

// pack two fp32 -> bf16x2 word: low 16 bits = x0, high = x1 (memory order: x0 first)
__device__ __forceinline__ uint32_t pkbf(float x0, float x1) {
    uint32_t r; asm("cvt.rn.bf16x2.f32 %0, %1, %2;" : "=r"(r) : "f"(x1), "f"(x0)); return r;
}

__device__ __forceinline__ void mma_bf16(float* d, const uint32_t* a, const uint32_t* b) {
    asm volatile(
        "mma.sync.aligned.m16n8k16.row.col.f32.bf16.bf16.f32 "
        "{%0,%1,%2,%3}, {%4,%5,%6,%7}, {%8,%9}, {%0,%1,%2,%3};\n"
        : "+f"(d[0]), "+f"(d[1]), "+f"(d[2]), "+f"(d[3])
        : "r"(a[0]), "r"(a[1]), "r"(a[2]), "r"(a[3]), "r"(b[0]), "r"(b[1]));
}

// ---------------- kernel: split W2 (= attn_W[:,1024:3072]) into bf16 hi/lo ----------------
// grid 4096, block 256; one bf16 pair per thread.
__global__ void split_w2_kernel(const float* __restrict__ attn_W) {
    int p = blockIdx.x * 256 + threadIdx.x;      // 1,048,576 pairs
    int h = p >> 10, kp = p & 1023;
    const float* src = attn_W + (size_t)h * 3072 + 1024 + kp * 2;
    float x0 = src[0], x1 = src[1];
    uint32_t hi = pkbf(x0, x1);
    float l0 = x0 - __uint_as_float(hi << 16);
    float l1 = x1 - __uint_as_float(hi & 0xffff0000u);
    uint32_t lo = pkbf(l0, l1);
    reinterpret_cast<uint32_t*>(g_W2hi)[p] = hi;
    reinterpret_cast<uint32_t*>(g_W2lo)[p] = lo;
}

// ---------------- kernel A: u[b,h] = attn_b[h] + sum_k hidden[b,k] * attn_W[h,k] ----------------
__global__ void u_kernel(const float* __restrict__ hidden, const float* __restrict__ attn_W,
                         const float* __restrict__ attn_b) {
    int w = threadIdx.x >> 5, lane = threadIdx.x & 31;
    int h = blockIdx.x * 8 + w;
    const float* Wr = attn_W + (size_t)h * 3072;  // first HH columns = W1
    float acc[32];
#pragma unroll
    for (int b = 0; b < 32; b++) acc[b] = 0.f;
    for (int kc = 0; kc < HH; kc += 32) {
        float wv = Wr[kc + lane];
#pragma unroll
        for (int b = 0; b < 32; b++) acc[b] += wv * __ldg(&hidden[b * HH + kc + lane]);
    }
    float bias = attn_b[h];
#pragma unroll
    for (int b = 0; b < 32; b++) {
        float s = acc[b];
#pragma unroll
        for (int o = 16; o; o >>= 1) s += __shfl_xor_sync(0xffffffffu, s, o);
        if (lane == b) g_u[b * HH + h] = s + bias;
    }
}

// ---------------- kernel: embed gather + hidden copy into transposed ziT ----------------
__global__ void embed_kernel(const int* __restrict__ x, const float* __restrict__ emb,
                             const float* __restrict__ hidden) {
    int b = blockIdx.x, t = threadIdx.x;
    int row = x[b];
    g_ziT[t * BB + b] = emb[(size_t)row * EE + t];                 // t in [0,512)
    for (int k = t; k < HH; k += 512)
        g_ziT[(2560 + k) * BB + b] = hidden[b * HH + k];
}

// ---------------- kernel B: fused scores via bf16 3-pass tensor-core GEMM ----------------
// grid (32 b, 8 s-tiles), 256 thr = 8 warps in 4(s) x 2(h) grid. Per ht (8): 128s x 128h tile,
// K=2048 in 32-chunks. SMEM rows padded to 40 bf16 (stride 20 words) -> conflict-free frag LDS.
#define RSTRIDE 20
__global__ void __launch_bounds__(256, 2)
score_kernel(const float* __restrict__ enc, const float* __restrict__ v_W) {
    __shared__ __align__(16) uint32_t As_hi[128 * RSTRIDE];
    __shared__ __align__(16) uint32_t As_lo[128 * RSTRIDE];
    __shared__ __align__(16) uint32_t Bs_hi[128 * RSTRIDE];
    __shared__ __align__(16) uint32_t Bs_lo[128 * RSTRIDE];
    __shared__ float us[128], vs[128];
    __shared__ float red[256];

    int b = blockIdx.x, st = blockIdx.y;
    const float* A = enc + ((size_t)b * SS + st * 128) * 2048;
    int tid = threadIdx.x;
    int w = tid >> 5, lane = tid & 31;
    int g = lane >> 2, tg = lane & 3;
    int wy = w >> 1, wx = w & 1;
    int m0 = wy * 32;
    int hb0 = wx * 64;

    float sc[2][2] = {{0.f, 0.f}, {0.f, 0.f}};

    for (int ht = 0; ht < 8; ht++) {
        int h0 = ht * 128;
        __syncthreads();  // previous epilogue done before us/vs overwrite
        if (tid < 128) { us[tid] = g_u[b * HH + h0 + tid]; vs[tid] = v_W[h0 + tid]; }

        float acc[2][8][4];
#pragma unroll
        for (int mi = 0; mi < 2; mi++)
#pragma unroll
            for (int nt = 0; nt < 8; nt++)
#pragma unroll
                for (int q = 0; q < 4; q++) acc[mi][nt][q] = 0.f;

        for (int kc = 0; kc < 2048; kc += 32) {
            __syncthreads();
            // A tile: load fp32, split to bf16 hi/lo (4 float4 per thread)
#pragma unroll
            for (int i = 0; i < 4; i++) {
                int idx = i * 256 + tid;
                int r = idx >> 3, f = idx & 7;
                float4 x = *(const float4*)&A[(size_t)r * 2048 + kc + f * 4];
                uint32_t h01 = pkbf(x.x, x.y);
                uint32_t h23 = pkbf(x.z, x.w);
                float l0 = x.x - __uint_as_float(h01 << 16);
                float l1 = x.y - __uint_as_float(h01 & 0xffff0000u);
                float l2 = x.z - __uint_as_float(h23 << 16);
                float l3 = x.w - __uint_as_float(h23 & 0xffff0000u);
                As_hi[r * RSTRIDE + f * 2]     = h01;
                As_hi[r * RSTRIDE + f * 2 + 1] = h23;
                As_lo[r * RSTRIDE + f * 2]     = pkbf(l0, l1);
                As_lo[r * RSTRIDE + f * 2 + 1] = pkbf(l2, l3);
            }
            // B tile: copy pre-split bf16 (2 uint4 per thread)
#pragma unroll
            for (int i = 0; i < 2; i++) {
                int idx = i * 256 + tid;
                int r = idx >> 2, q = idx & 3;
                const uint4* ph = reinterpret_cast<const uint4*>(g_W2hi + (size_t)(h0 + r) * 2048 + kc);
                const uint4* pl = reinterpret_cast<const uint4*>(g_W2lo + (size_t)(h0 + r) * 2048 + kc);
                reinterpret_cast<uint4*>(&Bs_hi[r * RSTRIDE])[q] = ph[q];
                reinterpret_cast<uint4*>(&Bs_lo[r * RSTRIDE])[q] = pl[q];
            }
            __syncthreads();
#pragma unroll
            for (int k16 = 0; k16 < 2; k16++) {
                int kw = k16 * 8 + tg;
                uint32_t Ah[2][4], Al[2][4];
#pragma unroll
                for (int mi = 0; mi < 2; mi++) {
                    int base = (m0 + mi * 16 + g) * RSTRIDE + kw;
                    Ah[mi][0] = As_hi[base];
                    Ah[mi][1] = As_hi[base + 8 * RSTRIDE];
                    Ah[mi][2] = As_hi[base + 4];
                    Ah[mi][3] = As_hi[base + 8 * RSTRIDE + 4];
                    Al[mi][0] = As_lo[base];
                    Al[mi][1] = As_lo[base + 8 * RSTRIDE];
                    Al[mi][2] = As_lo[base + 4];
                    Al[mi][3] = As_lo[base + 8 * RSTRIDE + 4];
                }
#pragma unroll
                for (int nt = 0; nt < 8; nt++) {
                    int bbase = (hb0 + nt * 8 + g) * RSTRIDE + kw;
                    uint32_t Bh[2] = {Bs_hi[bbase], Bs_hi[bbase + 4]};
                    uint32_t Bl[2] = {Bs_lo[bbase], Bs_lo[bbase + 4]};
#pragma unroll
                    for (int mi = 0; mi < 2; mi++) {
                        mma_bf16(acc[mi][nt], Ah[mi], Bh);
                        mma_bf16(acc[mi][nt], Ah[mi], Bl);
                        mma_bf16(acc[mi][nt], Al[mi], Bh);
                    }
                }
            }
        }
        // epilogue: tanh + v-weighted fold over this h-tile (us/vs ordered by kc-loop barriers)
#pragma unroll
        for (int mi = 0; mi < 2; mi++)
#pragma unroll
            for (int nt = 0; nt < 8; nt++) {
                int c = hb0 + nt * 8 + 2 * tg;
                float v0 = vs[c], v1 = vs[c + 1], u0 = us[c], u1 = us[c + 1];
                sc[mi][0] += v0 * tanhf(u0 + acc[mi][nt][0]) + v1 * tanhf(u1 + acc[mi][nt][1]);
                sc[mi][1] += v0 * tanhf(u0 + acc[mi][nt][2]) + v1 * tanhf(u1 + acc[mi][nt][3]);
            }
    }
    // reduce: over tg quad (fixed order), then across the 2 h-warps via SMEM
#pragma unroll
    for (int mi = 0; mi < 2; mi++)
#pragma unroll
        for (int hf = 0; hf < 2; hf++) {
            float v = sc[mi][hf];
            v += __shfl_xor_sync(0xffffffffu, v, 1);
            v += __shfl_xor_sync(0xffffffffu, v, 2);
            if (tg == 0) red[(m0 + mi * 16 + hf * 8 + g) * 2 + wx] = v;
        }
    __syncthreads();
    if (tid < 128)
        g_scores[b * SS + st * 128 + tid] = red[tid * 2] + red[tid * 2 + 1];
}

// ---------------- kernel C: softmax over S per batch; writes weights into d_out ----------------
__global__ void softmax_kernel(float* __restrict__ d_out) {
    int b = blockIdx.x, t = threadIdx.x;
    int lane = t & 31, wp = t >> 5;
    __shared__ float red[32];
    __shared__ float bc;
    float x = g_scores[b * SS + t];

    float m = x;
#pragma unroll
    for (int o = 16; o; o >>= 1) m = fmaxf(m, __shfl_xor_sync(0xffffffffu, m, o));
    if (!lane) red[wp] = m;
    __syncthreads();
    if (t < 32) {
        float mm = red[t];
#pragma unroll
        for (int o = 16; o; o >>= 1) mm = fmaxf(mm, __shfl_xor_sync(0xffffffffu, mm, o));
        if (!t) bc = mm;
    }
    __syncthreads();
    float M = bc;
    float e = __expf(x - M);
    __syncthreads();
    float s = e;
#pragma unroll
    for (int o = 16; o; o >>= 1) s += __shfl_xor_sync(0xffffffffu, s, o);
    if (!lane) red[wp] = s;
    __syncthreads();
    if (t < 32) {
        float ss = red[t];
#pragma unroll
        for (int o = 16; o; o >>= 1) ss += __shfl_xor_sync(0xffffffffu, ss, o);
        if (!t) bc = ss;
    }
    __syncthreads();
    d_out[OFF_W + b * SS + t] = e / bc;
}

// ---------------- kernel D: context[b,d] = sum_s w[b,s]*enc[b,s,d]; writes into ziT ----------------
__global__ void context_kernel(const float* __restrict__ enc, const float* __restrict__ d_out) {
    int b = blockIdx.y;
    int d = blockIdx.x * 256 + threadIdx.x;
    const float* E = enc + (size_t)b * SS * 2048 + d;
    const float* W = d_out + OFF_W + b * SS;
    float acc = 0.f;
    for (int s = 0; s < SS; s += 8) {
#pragma unroll
        for (int u = 0; u < 8; u++) acc += W[s + u] * E[(size_t)(s + u) * 2048];
    }
    g_ziT[(512 + d) * BB + b] = acc;
}

// ---------------- kernel E: gates GEMM: (4096 rows) x (32 b), K = 3584 ----------------
__global__ void gates_kernel(const float* __restrict__ W_ih, const float* __restrict__ W_hh,
                             const float* __restrict__ b_ih, const float* __restrict__ b_hh) {
    __shared__ float Ws[32][32];
    __shared__ float Zs[32][32];
    int tid = threadIdx.x;
    int tx = tid & 15, ty = tid >> 4;
    int g0 = blockIdx.x * 32;
    float acc[2][2] = {{0.f, 0.f}, {0.f, 0.f}};

    for (int kc = 0; kc < 3584; kc += 32) {
        __syncthreads();
#pragma unroll
        for (int l = 0; l < 4; l++) {
            int e = l * 256 + tid;
            int r = e >> 5, k = e & 31;
            int kg = kc + k;
            Ws[k][r] = (kc < 2560) ? W_ih[(size_t)(g0 + r) * 2560 + kg]
                                   : W_hh[(size_t)(g0 + r) * 1024 + kg - 2560];
            Zs[e >> 5][e & 31] = g_ziT[(size_t)kc * 32 + e];  // [K][b] tile
        }
        __syncthreads();
#pragma unroll
        for (int k = 0; k < 32; k++) {
            float a0 = Ws[k][ty * 2], a1 = Ws[k][ty * 2 + 1];
            float z0 = Zs[k][tx * 2], z1 = Zs[k][tx * 2 + 1];
            acc[0][0] += a0 * z0; acc[0][1] += a0 * z1;
            acc[1][0] += a1 * z0; acc[1][1] += a1 * z1;
        }
    }
#pragma unroll
    for (int i = 0; i < 2; i++) {
        int g = g0 + ty * 2 + i;
        float bias = b_ih[g] + b_hh[g];
#pragma unroll
        for (int j = 0; j < 2; j++) {
            int bcol = tx * 2 + j;
            g_gates[bcol * 4096 + g] = acc[i][j] + bias;
        }
    }
}

// ---------------- kernel: LSTM elementwise ----------------
__global__ void lstm_elt_kernel(const float* __restrict__ cell, float* __restrict__ d_out) {
    int idx = blockIdx.x * 256 + threadIdx.x;  // 32768
    int b = idx >> 10, h = idx & 1023;
    const float* g = g_gates + b * 4096;
    float gi = g[h], gf = g[1024 + h], gg = g[2048 + h], go = g[3072 + h];
    float c = cell[idx];
    float cn = sigf(gf) * c + sigf(gi) * tanhf(gg);
    float hn = sigf(go) * tanhf(cn);
    d_out[OFF_H + idx] = hn;
    d_out[OFF_C + idx] = cn;
    g_hnT[h * BB + b] = hn;
}

// ---------------- kernel F: fc GEMM: (32000 rows) x (32 b), K = 1024 ----------------
__global__ void fc_kernel(const float* __restrict__ fc_W, const float* __restrict__ fc_b,
                          float* __restrict__ d_out) {
    __shared__ __align__(16) float Ws[32][64];
    __shared__ __align__(16) float Zs[32][32];
    int tid = threadIdx.x;
    int tx = tid & 7, ty = tid >> 3;
    int v0 = blockIdx.x * 64;
    float acc[2][4];
#pragma unroll
    for (int i = 0; i < 2; i++)
#pragma unroll
        for (int j = 0; j < 4; j++) acc[i][j] = 0.f;

    for (int kc = 0; kc < 1024; kc += 32) {
        __syncthreads();
#pragma unroll
        for (int l = 0; l < 8; l++) {
            int e = l * 256 + tid;
            int r = e >> 5, k = e & 31;
            Ws[k][r] = fc_W[(size_t)(v0 + r) * 1024 + kc + k];
        }
#pragma unroll
        for (int l = 0; l < 4; l++) {
            int e = l * 256 + tid;
            Zs[e >> 5][e & 31] = g_hnT[(size_t)kc * 32 + e];
        }
        __syncthreads();
#pragma unroll
        for (int k = 0; k < 32; k++) {
            float a0 = Ws[k][ty * 2], a1 = Ws[k][ty * 2 + 1];
            float4 z = *(const float4*)&Zs[k][tx * 4];
            acc[0][0] += a0 * z.x; acc[0][1] += a0 * z.y; acc[0][2] += a0 * z.z; acc[0][3] += a0 * z.w;
            acc[1][0] += a1 * z.x; acc[1][1] += a1 * z.y; acc[1][2] += a1 * z.z; acc[1][3] += a1 * z.w;
        }
    }
#pragma unroll
    for (int i = 0; i < 2; i++) {
        int v = v0 + ty * 2 + i;
        float bias = fc_b[v];
#pragma unroll
        for (int j = 0; j < 4; j++) {
            int bcol = tx * 4 + j;
            d_out[OFF_PRED + (size_t)bcol * VV + v] = acc[i][j] + bias;
        }
    }
}

// ---------------- launcher ----------------
extern "C" void kernel_launch(void* const* d_in, const int* in_sizes, int n_in,
                              void* d_out_v, int out_size) {
    const int*   x      = (const int*)d_in[0];
    const float* hidden = (const float*)d_in[1];
    const float* cell   = (const float*)d_in[2];
    const float* enc    = (const float*)d_in[3];
    const float* emb    = (const float*)d_in[4];
    const float* attn_W = (const float*)d_in[5];
    const float* attn_b = (const float*)d_in[6];
    const float* v_W    = (const float*)d_in[7];
    const float* W_ih   = (const float*)d_in[8];
    const float* W_hh   = (const float*)d_in[9];
    const float* b_ih   = (const float*)d_in[10];
    const float* b_hh   = (const float*)d_in[11];
    const float* fc_W   = (const float*)d_in[12];
    const float* fc_b   = (const float*)d_in[13];
    float* d_out = (float*)d_out_v;

    split_w2_kernel<<<4096, 256>>>(attn_W);
    u_kernel<<<128, 256>>>(hidden, attn_W, attn_b);
    embed_kernel<<<32, 512>>>(x, emb, hidden);
    score_kernel<<<dim3(32, 8), 256>>>(enc, v_W);
    softmax_kernel<<<32, 1024>>>(d_out);
    context_kernel<<<dim3(8, 32), 256>>>(enc, d_out);
    gates_kernel<<<128, 256>>>(W_ih, W_hh, b_ih, b_hh);
    lstm_elt_kernel<<<128, 256>>>(cell, d_out);
    fc_kernel<<<500, 256>>>(fc_W, fc_b, d_out);
}

// round 11
// speedup vs baseline: 4.0285x; 1.0431x over previous
#include <cuda_runtime.h>
#include <cuda_bf16.h>
#include <cstdint>

// Problem constants
#define BB 32
#define SS 1024
#define HH 1024
#define EE 512
#define VV 32000
// Output layout (float32): prediction (B,1,V) | h_new (1,B,H) | c_new (1,B,H) | weights (B,S)
#define OFF_PRED 0
#define OFF_H    1024000
#define OFF_C    1056768
#define OFF_W    1089536

// ---------------- scratch (__device__ globals; no allocation allowed) ----------------
__device__ float g_u[BB * HH];          // W1 @ h + attn_b, per (b,h)
__device__ float g_scores[BB * SS];     // pre-softmax attention scores
__device__ float g_ziT[3584 * BB];      // [k][b] transposed LSTM input: emb(512)|context(2048)|hidden(1024)
__device__ float g_gates[BB * 4096];    // LSTM gates
__device__ float g_hnT[HH * BB];        // [h][b] transposed h_new for fc GEMM
__device__ __nv_bfloat16 g_W2hi[1024 * 2048];  // bf16 split of attn_W[:,1024:3072]
__device__ __nv_bfloat16 g_W2lo[1024 * 2048];

// ---------------- helpers ----------------
__device__ __forceinline__ float sigf(float x) { return 1.0f / (1.0f + __expf(-x)); }

// pack two fp32 -> bf16x2 word: low 16 bits = x0, high = x1 (memory order: x0 first)
__device__ __forceinline__ uint32_t pkbf(float x0, float x1) {
    uint32_t r; asm("cvt.rn.bf16x2.f32 %0, %1, %2;" : "=r"(r) : "f"(x1), "f"(x0)); return r;
}

__device__ __forceinline__ void mma_bf16(float* d, const uint32_t* a, const uint32_t* b) {
    asm volatile(
        "mma.sync.aligned.m16n8k16.row.col.f32.bf16.bf16.f32 "
        "{%0,%1,%2,%3}, {%4,%5,%6,%7}, {%8,%9}, {%0,%1,%2,%3};\n"
        : "+f"(d[0]), "+f"(d[1]), "+f"(d[2]), "+f"(d[3])
        : "r"(a[0]), "r"(a[1]), "r"(a[2]), "r"(a[3]), "r"(b[0]), "r"(b[1]));
}

__device__ __forceinline__ uint32_t smem_u32(const void* p) {
    uint32_t a;
    asm("{ .reg .u64 t; cvta.to.shared.u64 t, %1; cvt.u32.u64 %0, t; }" : "=r"(a) : "l"(p));
    return a;
}
__device__ __forceinline__ void cpa16(uint32_t dst, const void* src) {
    asm volatile("cp.async.cg.shared.global [%0], [%1], 16;" :: "r"(dst), "l"(src));
}
__device__ __forceinline__ void cpa_commit() {
    asm volatile("cp.async.commit_group;" ::: "memory");
}
__device__ __forceinline__ void cpa_wait_all() {
    asm volatile("cp.async.wait_group 0;" ::: "memory");
}

// ---------------- kernel: split W2 (= attn_W[:,1024:3072]) into bf16 hi/lo ----------------
__global__ void split_w2_kernel(const float* __restrict__ attn_W) {
    int p = blockIdx.x * 256 + threadIdx.x;      // 1,048,576 pairs
    int h = p >> 10, kp = p & 1023;
    const float* src = attn_W + (size_t)h * 3072 + 1024 + kp * 2;
    float x0 = src[0], x1 = src[1];
    uint32_t hi = pkbf(x0, x1);
    float l0 = x0 - __uint_as_float(hi << 16);
    float l1 = x1 - __uint_as_float(hi & 0xffff0000u);
    uint32_t lo = pkbf(l0, l1);
    reinterpret_cast<uint32_t*>(g_W2hi)[p] = hi;
    reinterpret_cast<uint32_t*>(g_W2lo)[p] = lo;
}

// ---------------- kernel A: u[b,h] = attn_b[h] + sum_k hidden[b,k] * attn_W[h,k] ----------------
__global__ void u_kernel(const float* __restrict__ hidden, const float* __restrict__ attn_W,
                         const float* __restrict__ attn_b) {
    int w = threadIdx.x >> 5, lane = threadIdx.x & 31;
    int h = blockIdx.x * 8 + w;
    const float* Wr = attn_W + (size_t)h * 3072;  // first HH columns = W1
    float acc[32];
#pragma unroll
    for (int b = 0; b < 32; b++) acc[b] = 0.f;
    for (int kc = 0; kc < HH; kc += 32) {
        float wv = Wr[kc + lane];
#pragma unroll
        for (int b = 0; b < 32; b++) acc[b] += wv * __ldg(&hidden[b * HH + kc + lane]);
    }
    float bias = attn_b[h];
#pragma unroll
    for (int b = 0; b < 32; b++) {
        float s = acc[b];
#pragma unroll
        for (int o = 16; o; o >>= 1) s += __shfl_xor_sync(0xffffffffu, s, o);
        if (lane == b) g_u[b * HH + h] = s + bias;
    }
}

// ---------------- kernel: embed gather + hidden copy into transposed ziT ----------------
__global__ void embed_kernel(const int* __restrict__ x, const float* __restrict__ emb,
                             const float* __restrict__ hidden) {
    int b = blockIdx.x, t = threadIdx.x;
    int row = x[b];
    g_ziT[t * BB + b] = emb[(size_t)row * EE + t];                 // t in [0,512)
    for (int k = t; k < HH; k += 512)
        g_ziT[(2560 + k) * BB + b] = hidden[b * HH + k];
}

// ---------------- kernel B: fused scores, bf16 3-pass mma.sync, double-buffered pipeline ----
// grid (32 b, 8 st), 256 thr = 8 warps (4 s x 2 h). Tile 128s x 128h per ht, K=2048 in
// 32-k chunks. Dynamic SMEM: 2 stages x {A_hi,A_lo,B_hi,B_lo} with RSTRIDE-20 padded rows
// (conflict-free fragment LDS). A prefetched via registers; B via cp.async (pre-split).
#define RSTRIDE 20
#define STG_BYTES 40960u
#define A_HI_OFF(s) ((s) * STG_BYTES + 0u)
#define A_LO_OFF(s) ((s) * STG_BYTES + 10240u)
#define B_HI_OFF(s) ((s) * STG_BYTES + 20480u)
#define B_LO_OFF(s) ((s) * STG_BYTES + 30720u)
#define US_OFF  81920u
#define VS_OFF  82432u
#define RED_OFF 82944u
#define SC_SMEM 83968

__global__ void __launch_bounds__(256, 2)
score_kernel(const float* __restrict__ enc, const float* __restrict__ v_W) {
    extern __shared__ __align__(16) char smem[];
    uint32_t sbase = smem_u32(smem);
    float* usp = (float*)(smem + US_OFF);
    float* vsp = (float*)(smem + VS_OFF);
    float* red = (float*)(smem + RED_OFF);

    int b = blockIdx.x, st = blockIdx.y;
    const float* A = enc + ((size_t)b * SS + st * 128) * 2048;
    int tid = threadIdx.x;
    int w = tid >> 5, lane = tid & 31;
    int g = lane >> 2, tg = lane & 3;
    int wy = w >> 1, wx = w & 1;
    int m0 = wy * 32;
    int hb0 = wx * 64;

    float sc[2][2] = {{0.f, 0.f}, {0.f, 0.f}};

    for (int ht = 0; ht < 8; ht++) {
        int h0 = ht * 128;
        __syncthreads();  // all reads of both stages + us/vs complete
        if (tid < 128) { usp[tid] = g_u[b * HH + h0 + tid]; vsp[tid] = v_W[h0 + tid]; }

        float acc[2][8][4];
#pragma unroll
        for (int mi = 0; mi < 2; mi++)
#pragma unroll
            for (int nt = 0; nt < 8; nt++)
#pragma unroll
                for (int q = 0; q < 4; q++) acc[mi][nt][q] = 0.f;

        float4 ra[4];
        // ---- prologue: chunk 0 ----
#pragma unroll
        for (int j = 0; j < 4; j++) {
            int e = j * 256 + tid, r = e >> 3, f = e & 7;
            ra[j] = *(const float4*)&A[(size_t)r * 2048 + f * 4];
        }
#pragma unroll
        for (int j = 0; j < 2; j++) {
            int e = j * 256 + tid, r = e >> 2, q = e & 3;
            cpa16(sbase + B_HI_OFF(0) + r * 80 + q * 16,
                  g_W2hi + (size_t)(h0 + r) * 2048 + q * 8);
            cpa16(sbase + B_LO_OFF(0) + r * 80 + q * 16,
                  g_W2lo + (size_t)(h0 + r) * 2048 + q * 8);
        }
        cpa_commit();
#pragma unroll
        for (int j = 0; j < 4; j++) {
            int e = j * 256 + tid, r = e >> 3, f = e & 7;
            float4 x = ra[j];
            uint32_t h01 = pkbf(x.x, x.y), h23 = pkbf(x.z, x.w);
            float l0 = x.x - __uint_as_float(h01 << 16);
            float l1 = x.y - __uint_as_float(h01 & 0xffff0000u);
            float l2 = x.z - __uint_as_float(h23 << 16);
            float l3 = x.w - __uint_as_float(h23 & 0xffff0000u);
            *(uint2*)(smem + A_HI_OFF(0) + r * 80 + f * 8) = make_uint2(h01, h23);
            *(uint2*)(smem + A_LO_OFF(0) + r * 80 + f * 8) = make_uint2(pkbf(l0, l1), pkbf(l2, l3));
        }

        for (int i = 0; i < 64; i++) {
            int s = i & 1;
            // prefetch next A chunk into registers (latency hidden by compute below)
            if (i < 63) {
                const float* Ab = A + (i + 1) * 32;
#pragma unroll
                for (int j = 0; j < 4; j++) {
                    int e = j * 256 + tid, r = e >> 3, f = e & 7;
                    ra[j] = *(const float4*)&Ab[(size_t)r * 2048 + f * 4];
                }
            }
            cpa_wait_all();    // B(i) landed
            __syncthreads();   // A(i) STS visible; prior readers of stage s^1 done
            if (i < 63) {      // issue B(i+1) AFTER barrier (no race with stage s^1 readers)
                int kc = (i + 1) * 32;
#pragma unroll
                for (int j = 0; j < 2; j++) {
                    int e = j * 256 + tid, r = e >> 2, q = e & 3;
                    cpa16(sbase + B_HI_OFF(s ^ 1) + r * 80 + q * 16,
                          g_W2hi + (size_t)(h0 + r) * 2048 + kc + q * 8);
                    cpa16(sbase + B_LO_OFF(s ^ 1) + r * 80 + q * 16,
                          g_W2lo + (size_t)(h0 + r) * 2048 + kc + q * 8);
                }
                cpa_commit();
            }
            // ---- compute chunk i from stage s ----
            {
                const uint32_t* AsH = (const uint32_t*)(smem + A_HI_OFF(s));
                const uint32_t* AsL = (const uint32_t*)(smem + A_LO_OFF(s));
                const uint32_t* BsH = (const uint32_t*)(smem + B_HI_OFF(s));
                const uint32_t* BsL = (const uint32_t*)(smem + B_LO_OFF(s));
#pragma unroll
                for (int k16 = 0; k16 < 2; k16++) {
                    int kw = k16 * 8 + tg;
                    uint32_t Ah[2][4], Al[2][4];
#pragma unroll
                    for (int mi = 0; mi < 2; mi++) {
                        int base = (m0 + mi * 16 + g) * RSTRIDE + kw;
                        Ah[mi][0] = AsH[base];
                        Ah[mi][1] = AsH[base + 8 * RSTRIDE];
                        Ah[mi][2] = AsH[base + 4];
                        Ah[mi][3] = AsH[base + 8 * RSTRIDE + 4];
                        Al[mi][0] = AsL[base];
                        Al[mi][1] = AsL[base + 8 * RSTRIDE];
                        Al[mi][2] = AsL[base + 4];
                        Al[mi][3] = AsL[base + 8 * RSTRIDE + 4];
                    }
#pragma unroll
                    for (int nt = 0; nt < 8; nt++) {
                        int bbase = (hb0 + nt * 8 + g) * RSTRIDE + kw;
                        uint32_t Bh[2] = {BsH[bbase], BsH[bbase + 4]};
                        uint32_t Bl[2] = {BsL[bbase], BsL[bbase + 4]};
#pragma unroll
                        for (int mi = 0; mi < 2; mi++) {
                            mma_bf16(acc[mi][nt], Ah[mi], Bh);
                            mma_bf16(acc[mi][nt], Ah[mi], Bl);
                            mma_bf16(acc[mi][nt], Al[mi], Bh);
                        }
                    }
                }
            }
            // ---- store prefetched A into the other stage ----
            if (i < 63) {
#pragma unroll
                for (int j = 0; j < 4; j++) {
                    int e = j * 256 + tid, r = e >> 3, f = e & 7;
                    float4 x = ra[j];
                    uint32_t h01 = pkbf(x.x, x.y), h23 = pkbf(x.z, x.w);
                    float l0 = x.x - __uint_as_float(h01 << 16);
                    float l1 = x.y - __uint_as_float(h01 & 0xffff0000u);
                    float l2 = x.z - __uint_as_float(h23 << 16);
                    float l3 = x.w - __uint_as_float(h23 & 0xffff0000u);
                    *(uint2*)(smem + A_HI_OFF(s ^ 1) + r * 80 + f * 8) = make_uint2(h01, h23);
                    *(uint2*)(smem + A_LO_OFF(s ^ 1) + r * 80 + f * 8) =
                        make_uint2(pkbf(l0, l1), pkbf(l2, l3));
                }
            }
        }
        // ---- epilogue: tanh + v-weighted fold over this h-tile ----
#pragma unroll
        for (int mi = 0; mi < 2; mi++)
#pragma unroll
            for (int nt = 0; nt < 8; nt++) {
                int c = hb0 + nt * 8 + 2 * tg;
                float v0 = vsp[c], v1 = vsp[c + 1], u0 = usp[c], u1 = usp[c + 1];
                sc[mi][0] += v0 * tanhf(u0 + acc[mi][nt][0]) + v1 * tanhf(u1 + acc[mi][nt][1]);
                sc[mi][1] += v0 * tanhf(u0 + acc[mi][nt][2]) + v1 * tanhf(u1 + acc[mi][nt][3]);
            }
    }
    // reduce: over tg quad (fixed order), then across the 2 h-warps via SMEM
#pragma unroll
    for (int mi = 0; mi < 2; mi++)
#pragma unroll
        for (int hf = 0; hf < 2; hf++) {
            float v = sc[mi][hf];
            v += __shfl_xor_sync(0xffffffffu, v, 1);
            v += __shfl_xor_sync(0xffffffffu, v, 2);
            if (tg == 0) red[(m0 + mi * 16 + hf * 8 + g) * 2 + wx] = v;
        }
    __syncthreads();
    if (tid < 128)
        g_scores[b * SS + st * 128 + tid] = red[tid * 2] + red[tid * 2 + 1];
}

// ---------------- kernel C: softmax over S per batch; writes weights into d_out ----------------
__global__ void softmax_kernel(float* __restrict__ d_out) {
    int b = blockIdx.x, t = threadIdx.x;
    int lane = t & 31, wp = t >> 5;
    __shared__ float red[32];
    __shared__ float bc;
    float x = g_scores[b * SS + t];

    float m = x;
#pragma unroll
    for (int o = 16; o; o >>= 1) m = fmaxf(m, __shfl_xor_sync(0xffffffffu, m, o));
    if (!lane) red[wp] = m;
    __syncthreads();
    if (t < 32) {
        float mm = red[t];
#pragma unroll
        for (int o = 16; o; o >>= 1) mm = fmaxf(mm, __shfl_xor_sync(0xffffffffu, mm, o));
        if (!t) bc = mm;
    }
    __syncthreads();
    float M = bc;
    float e = __expf(x - M);
    __syncthreads();
    float s = e;
#pragma unroll
    for (int o = 16; o; o >>= 1) s += __shfl_xor_sync(0xffffffffu, s, o);
    if (!lane) red[wp] = s;
    __syncthreads();
    if (t < 32) {
        float ss = red[t];
#pragma unroll
        for (int o = 16; o; o >>= 1) ss += __shfl_xor_sync(0xffffffffu, ss, o);
        if (!t) bc = ss;
    }
    __syncthreads();
    d_out[OFF_W + b * SS + t] = e / bc;
}

// ---------------- kernel D: context[b,d] = sum_s w[b,s]*enc[b,s,d]; writes into ziT ----------------
__global__ void context_kernel(const float* __restrict__ enc, const float* __restrict__ d_out) {
    int b = blockIdx.y;
    int d = blockIdx.x * 256 + threadIdx.x;
    const float* E = enc + (size_t)b * SS * 2048 + d;
    const float* W = d_out + OFF_W + b * SS;
    float acc = 0.f;
    for (int s = 0; s < SS; s += 8) {
#pragma unroll
        for (int u = 0; u < 8; u++) acc += W[s + u] * E[(size_t)(s + u) * 2048];
    }
    g_ziT[(512 + d) * BB + b] = acc;
}

// ---------------- kernel E: gates GEMM: (4096 rows) x (32 b), K = 3584 ----------------
__global__ void gates_kernel(const float* __restrict__ W_ih, const float* __restrict__ W_hh,
                             const float* __restrict__ b_ih, const float* __restrict__ b_hh) {
    __shared__ float Ws[32][32];
    __shared__ float Zs[32][32];
    int tid = threadIdx.x;
    int tx = tid & 15, ty = tid >> 4;
    int g0 = blockIdx.x * 32;
    float acc[2][2] = {{0.f, 0.f}, {0.f, 0.f}};

    for (int kc = 0; kc < 3584; kc += 32) {
        __syncthreads();
#pragma unroll
        for (int l = 0; l < 4; l++) {
            int e = l * 256 + tid;
            int r = e >> 5, k = e & 31;
            int kg = kc + k;
            Ws[k][r] = (kc < 2560) ? W_ih[(size_t)(g0 + r) * 2560 + kg]
                                   : W_hh[(size_t)(g0 + r) * 1024 + kg - 2560];
            Zs[e >> 5][e & 31] = g_ziT[(size_t)kc * 32 + e];  // [K][b] tile
        }
        __syncthreads();
#pragma unroll
        for (int k = 0; k < 32; k++) {
            float a0 = Ws[k][ty * 2], a1 = Ws[k][ty * 2 + 1];
            float z0 = Zs[k][tx * 2], z1 = Zs[k][tx * 2 + 1];
            acc[0][0] += a0 * z0; acc[0][1] += a0 * z1;
            acc[1][0] += a1 * z0; acc[1][1] += a1 * z1;
        }
    }
#pragma unroll
    for (int i = 0; i < 2; i++) {
        int g = g0 + ty * 2 + i;
        float bias = b_ih[g] + b_hh[g];
#pragma unroll
        for (int j = 0; j < 2; j++) {
            int bcol = tx * 2 + j;
            g_gates[bcol * 4096 + g] = acc[i][j] + bias;
        }
    }
}

// ---------------- kernel: LSTM elementwise ----------------
__global__ void lstm_elt_kernel(const float* __restrict__ cell, float* __restrict__ d_out) {
    int idx = blockIdx.x * 256 + threadIdx.x;  // 32768
    int b = idx >> 10, h = idx & 1023;
    const float* g = g_gates + b * 4096;
    float gi = g[h], gf = g[1024 + h], gg = g[2048 + h], go = g[3072 + h];
    float c = cell[idx];
    float cn = sigf(gf) * c + sigf(gi) * tanhf(gg);
    float hn = sigf(go) * tanhf(cn);
    d_out[OFF_H + idx] = hn;
    d_out[OFF_C + idx] = cn;
    g_hnT[h * BB + b] = hn;
}

// ---------------- kernel F: fc GEMM: (32000 rows) x (32 b), K = 1024 ----------------
__global__ void fc_kernel(const float* __restrict__ fc_W, const float* __restrict__ fc_b,
                          float* __restrict__ d_out) {
    __shared__ __align__(16) float Ws[32][64];
    __shared__ __align__(16) float Zs[32][32];
    int tid = threadIdx.x;
    int tx = tid & 7, ty = tid >> 3;
    int v0 = blockIdx.x * 64;
    float acc[2][4];
#pragma unroll
    for (int i = 0; i < 2; i++)
#pragma unroll
        for (int j = 0; j < 4; j++) acc[i][j] = 0.f;

    for (int kc = 0; kc < 1024; kc += 32) {
        __syncthreads();
#pragma unroll
        for (int l = 0; l < 8; l++) {
            int e = l * 256 + tid;
            int r = e >> 5, k = e & 31;
            Ws[k][r] = fc_W[(size_t)(v0 + r) * 1024 + kc + k];
        }
#pragma unroll
        for (int l = 0; l < 4; l++) {
            int e = l * 256 + tid;
            Zs[e >> 5][e & 31] = g_hnT[(size_t)kc * 32 + e];
        }
        __syncthreads();
#pragma unroll
        for (int k = 0; k < 32; k++) {
            float a0 = Ws[k][ty * 2], a1 = Ws[k][ty * 2 + 1];
            float4 z = *(const float4*)&Zs[k][tx * 4];
            acc[0][0] += a0 * z.x; acc[0][1] += a0 * z.y; acc[0][2] += a0 * z.z; acc[0][3] += a0 * z.w;
            acc[1][0] += a1 * z.x; acc[1][1] += a1 * z.y; acc[1][2] += a1 * z.z; acc[1][3] += a1 * z.w;
        }
    }
#pragma unroll
    for (int i = 0; i < 2; i++) {
        int v = v0 + ty * 2 + i;
        float bias = fc_b[v];
#pragma unroll
        for (int j = 0; j < 4; j++) {
            int bcol = tx * 4 + j;
            d_out[OFF_PRED + (size_t)bcol * VV + v] = acc[i][j] + bias;
        }
    }
}

// ---------------- launcher ----------------
extern "C" void kernel_launch(void* const* d_in, const int* in_sizes, int n_in,
                              void* d_out_v, int out_size) {
    const int*   x      = (const int*)d_in[0];
    const float* hidden = (const float*)d_in[1];
    const float* cell   = (const float*)d_in[2];
    const float* enc    = (const float*)d_in[3];
    const float* emb    = (const float*)d_in[4];
    const float* attn_W = (const float*)d_in[5];
    const float* attn_b = (const float*)d_in[6];
    const float* v_W    = (const float*)d_in[7];
    const float* W_ih   = (const float*)d_in[8];
    const float* W_hh   = (const float*)d_in[9];
    const float* b_ih   = (const float*)d_in[10];
    const float* b_hh   = (const float*)d_in[11];
    const float* fc_W   = (const float*)d_in[12];
    const float* fc_b   = (const float*)d_in[13];
    float* d_out = (float*)d_out_v;

    static bool attr_done = false;
    if (!attr_done) {
        cudaFuncSetAttribute(score_kernel, cudaFuncAttributeMaxDynamicSharedMemorySize, SC_SMEM);
        attr_done = true;
    }

    split_w2_kernel<<<4096, 256>>>(attn_W);
    u_kernel<<<128, 256>>>(hidden, attn_W, attn_b);
    embed_kernel<<<32, 512>>>(x, emb, hidden);
    score_kernel<<<dim3(32, 8), 256, SC_SMEM>>>(enc, v_W);
    softmax_kernel<<<32, 1024>>>(d_out);
    context_kernel<<<dim3(8, 32), 256>>>(enc, d_out);
    gates_kernel<<<128, 256>>>(W_ih, W_hh, b_ih, b_hh);
    lstm_elt_kernel<<<128, 256>>>(cell, d_out);
    fc_kernel<<<500, 256>>>(fc_W, fc_b, d_out);
}